// round 17
// baseline (speedup 1.0000x reference)
#include <cuda_runtime.h>

#define EPS 1e-6f
#define Q 128
#define HW 65536            // 256*256
#define NCOLS 32            // columns per block (4 per warp)
#define THREADS 256
#define ASTRIDE 132         // words per column in staging arrays

__device__ float g_wt[Q];   // softmax(weights) * 128, precomputed once

__global__ void softmax_wt_kernel(const float* __restrict__ w) {
    int l = threadIdx.x;
    float v0 = w[l * 4 + 0], v1 = w[l * 4 + 1];
    float v2 = w[l * 4 + 2], v3 = w[l * 4 + 3];
    float m = fmaxf(fmaxf(v0, v1), fmaxf(v2, v3));
    #pragma unroll
    for (int o = 16; o; o >>= 1) m = fmaxf(m, __shfl_xor_sync(0xffffffffu, m, o));
    float e0 = expf(v0 - m), e1 = expf(v1 - m);
    float e2 = expf(v2 - m), e3 = expf(v3 - m);
    float s = e0 + e1 + e2 + e3;
    #pragma unroll
    for (int o = 16; o; o >>= 1) s += __shfl_xor_sync(0xffffffffu, s, o);
    float scale = 128.0f / s;
    g_wt[l * 4 + 0] = e0 * scale;
    g_wt[l * 4 + 1] = e1 * scale;
    g_wt[l * 4 + 2] = e2 * scale;
    g_wt[l * 4 + 3] = e3 * scale;
}

// orderable-uint transform: monotonic with float order (no NaN in inputs)
__device__ __forceinline__ unsigned ford(unsigned b) {
    return b ^ ((unsigned)(((int)b) >> 31) | 0x80000000u);
}

// unsigned compare-exchange helpers (predicated IMNMX form)
#define UCE_D(i,jj) { unsigned _a=v[i], _b=v[jj]; v[i]=max(_a,_b); v[jj]=min(_a,_b); }
#define UCE_A(i,jj) { unsigned _a=v[i], _b=v[jj]; v[i]=min(_a,_b); v[jj]=max(_a,_b); }
#define UCE_P(i,jj,p) { unsigned _a=v[i], _b=v[jj]; unsigned _mx=max(_a,_b), _mn=min(_a,_b); \
                        v[i]=(p)?_mx:_mn; v[jj]=(p)?_mn:_mx; }
// full in-register bitonic merge of 16 (j = 8,4,2,1), single predicate
#define UINREG16_P(p) \
    UCE_P(0,8,p) UCE_P(1,9,p) UCE_P(2,10,p) UCE_P(3,11,p) \
    UCE_P(4,12,p) UCE_P(5,13,p) UCE_P(6,14,p) UCE_P(7,15,p) \
    UCE_P(0,4,p) UCE_P(1,5,p) UCE_P(2,6,p) UCE_P(3,7,p) \
    UCE_P(8,12,p) UCE_P(9,13,p) UCE_P(10,14,p) UCE_P(11,15,p) \
    UCE_P(0,2,p) UCE_P(1,3,p) UCE_P(4,6,p) UCE_P(5,7,p) \
    UCE_P(8,10,p) UCE_P(9,11,p) UCE_P(12,14,p) UCE_P(13,15,p) \
    UCE_P(0,1,p) UCE_P(2,3,p) UCE_P(4,5,p) UCE_P(6,7,p) \
    UCE_P(8,9,p) UCE_P(10,11,p) UCE_P(12,13,p) UCE_P(14,15,p)
#define UINREG16_D() \
    UCE_D(0,8) UCE_D(1,9) UCE_D(2,10) UCE_D(3,11) \
    UCE_D(4,12) UCE_D(5,13) UCE_D(6,14) UCE_D(7,15) \
    UCE_D(0,4) UCE_D(1,5) UCE_D(2,6) UCE_D(3,7) \
    UCE_D(8,12) UCE_D(9,13) UCE_D(10,14) UCE_D(11,15) \
    UCE_D(0,2) UCE_D(1,3) UCE_D(4,6) UCE_D(5,7) \
    UCE_D(8,10) UCE_D(9,11) UCE_D(12,14) UCE_D(13,15) \
    UCE_D(0,1) UCE_D(2,3) UCE_D(4,5) UCE_D(6,7) \
    UCE_D(8,9) UCE_D(10,11) UCE_D(12,13) UCE_D(14,15)
#define XSTAGE16(ld, km) { \
    _Pragma("unroll") \
    for (int _r = 0; _r < 16; _r++) { \
        unsigned _o = __shfl_xor_sync(0xffffffffu, v[_r], (ld)); \
        v[_r] = (km) ? max(v[_r], _o) : min(v[_r], _o); \
    } }

// ---------------------------------------------------------------------------
// 256 threads = 8 warps; each warp ranks FOUR columns of 128.
// Lane mapping: c = lane&3 (column within warp), m = lane>>2 (0..7).
// Each lane holds 16 elements q = 16m + r. Keys = ford(x) with low 7 bits
// = 127-idx  ->  sort IS the rank+provenance. A holds originals; W receives
// scattered weights; rsqrt fused into the output transpose.
// ---------------------------------------------------------------------------
__global__ void __launch_bounds__(THREADS, 5) rank_weight_kernel(
        const float* __restrict__ x, float* __restrict__ out) {
    __shared__ __align__(16) float A[NCOLS * ASTRIDE];  // originals
    __shared__ __align__(16) float W[NCOLS * ASTRIDE];  // scattered weights

    int t    = threadIdx.x;
    int lane = t & 31;
    int w    = t >> 5;
    int c    = lane & 3;          // column within warp
    int m    = lane >> 2;         // lane index within column (0..7)

    long long c0  = (long long)blockIdx.x * NCOLS;
    int       b   = (int)(c0 >> 16);
    int       rem = (int)(c0 & (HW - 1));
    const float* xb = x   + (long long)b * (Q * (long long)HW) + rem;
    float*       ob = out + (long long)b * (Q * (long long)HW) + rem;

    // ---- Phase 1: coalesced load, transpose into SMEM ----
    // A[col][q] at word col*132 + q; store instr (blk,j): banks 16g+4j+q -> CF
    {
        int q = t >> 1, g = t & 1;
        #pragma unroll
        for (int blk = 0; blk < 4; blk++) {
            float4 f = *reinterpret_cast<const float4*>(
                           xb + (long long)q * HW + 8 * blk + 4 * g);
            int cb = (8 * blk + 4 * g) * ASTRIDE + q;
            A[cb]               = f.x;
            A[cb + ASTRIDE]     = f.y;
            A[cb + 2 * ASTRIDE] = f.z;
            A[cb + 3 * ASTRIDE] = f.w;
        }
    }
    __syncthreads();

    // ---- Phase 2: read own slice (q = 16m..16m+15), build keys ----
    int colw = (4 * w + c) * ASTRIDE;
    unsigned v[16];
    {
        int base = 127 - 16 * m;
        #pragma unroll
        for (int u = 0; u < 4; u++) {
            float4 f = *reinterpret_cast<const float4*>(&A[colw + 16 * m + 4 * u]);
            v[4*u+0] = (ford(__float_as_uint(f.x)) & 0xFFFFFF80u) + (unsigned)(base - 4*u - 0);
            v[4*u+1] = (ford(__float_as_uint(f.y)) & 0xFFFFFF80u) + (unsigned)(base - 4*u - 1);
            v[4*u+2] = (ford(__float_as_uint(f.z)) & 0xFFFFFF80u) + (unsigned)(base - 4*u - 2);
            v[4*u+3] = (ford(__float_as_uint(f.w)) & 0xFFFFFF80u) + (unsigned)(base - 4*u - 3);
        }
    }

    // ---- bitonic sort over i = 16m + r, descending on keys ----
    // k=2
    UCE_D(0,1) UCE_A(2,3) UCE_D(4,5) UCE_A(6,7)
    UCE_D(8,9) UCE_A(10,11) UCE_D(12,13) UCE_A(14,15)
    // k=4
    UCE_D(0,2) UCE_D(1,3) UCE_A(4,6) UCE_A(5,7)
    UCE_D(8,10) UCE_D(9,11) UCE_A(12,14) UCE_A(13,15)
    UCE_D(0,1) UCE_D(2,3) UCE_A(4,5) UCE_A(6,7)
    UCE_D(8,9) UCE_D(10,11) UCE_A(12,13) UCE_A(14,15)
    // k=8
    UCE_D(0,4) UCE_D(1,5) UCE_D(2,6) UCE_D(3,7)
    UCE_A(8,12) UCE_A(9,13) UCE_A(10,14) UCE_A(11,15)
    UCE_D(0,2) UCE_D(1,3) UCE_D(4,6) UCE_D(5,7)
    UCE_A(8,10) UCE_A(9,11) UCE_A(12,14) UCE_A(13,15)
    UCE_D(0,1) UCE_D(2,3) UCE_D(4,5) UCE_D(6,7)
    UCE_A(8,9) UCE_A(10,11) UCE_A(12,13) UCE_A(14,15)
    // k=16 (fully in-register, predicate per lane)
    {   bool p = (m & 1) == 0;
        UINREG16_P(p)
    }
    // k=32
    {   bool p = (m & 2) == 0;
        XSTAGE16(4, p == ((m & 1) == 0))
        UINREG16_P(p)
    }
    // k=64
    {   bool p = (m & 4) == 0;
        XSTAGE16(8, p == ((m & 2) == 0))
        XSTAGE16(4, p == ((m & 1) == 0))
        UINREG16_P(p)
    }
    // k=128 (descending everywhere)
    XSTAGE16(16, (m & 4) == 0)
    XSTAGE16(8,  (m & 2) == 0)
    XSTAGE16(4,  (m & 1) == 0)
    UINREG16_D()

    // ---- clobber detection: adjacent sorted keys equal in high 25 bits ----
    unsigned knext = __shfl_down_sync(0xffffffffu, v[0], 4);   // next m, same c
    unsigned kprev = __shfl_up_sync(0xffffffffu, v[15], 4);
    bool fl[15];
    #pragma unroll
    for (int r = 0; r < 15; r++) fl[r] = (v[r] ^ v[r + 1]) < 128u;
    bool flagB = (m < 7) && ((v[15] ^ knext) < 128u);
    unsigned fpv = __shfl_up_sync(0xffffffffu, (unsigned)flagB, 4);
    bool fprev = (m > 0) && (fpv != 0u);

    bool anyf = fprev | flagB, badf = false;
    #pragma unroll
    for (int r = 0; r < 15; r++) anyf |= fl[r];
    {   // badf: some element has flags on both sides (run >= 3)
        bool p0 = fprev & fl[0];
        #pragma unroll
        for (int r = 1; r < 15; r++) p0 |= (fl[r - 1] & fl[r]);
        p0 |= (fl[14] & flagB);
        badf = p0;
    }

    unsigned anyb = __ballot_sync(0xffffffffu, anyf);
    unsigned badb = anyb ? __ballot_sync(0xffffffffu, badf) : 0u;
    unsigned colmask = 0x11111111u << c;

    // ---- scatter weights: W[idx] = g_wt[sorted position] ----
    #pragma unroll
    for (int u = 0; u < 4; u++) {
        float4 wf = *reinterpret_cast<const float4*>(&g_wt[16 * m + 4 * u]);
        W[colw + (int)((~v[4*u+0]) & 127u)] = wf.x;
        W[colw + (int)((~v[4*u+1]) & 127u)] = wf.y;
        W[colw + (int)((~v[4*u+2]) & 127u)] = wf.z;
        W[colw + (int)((~v[4*u+3]) & 127u)] = wf.w;
    }

    // ---- rare fixes overwrite W (same-lane order: fix lands after scatter) ----
    if (anyb & colmask) {
        if (badb & colmask) {
            // run >= 3 in this column: exact recount for all 16 elements
            #pragma unroll 1
            for (int r = 0; r < 16; r++) {
                int idx = (int)((~v[r]) & 127u);
                unsigned us = ford(__float_as_uint(A[colw + idx]));
                int gt = 0, eq = 0;
                for (int jj = 0; jj < Q; jj++) {
                    unsigned ua = ford(__float_as_uint(A[colw + jj]));
                    gt += (ua > us) ? 1 : 0;
                    eq += ((ua == us) && (jj < idx)) ? 1 : 0;
                }
                W[colw + idx] = g_wt[gt + eq];
            }
        } else {
            // pair runs only: exact 2-element fix per flagged element
            #pragma unroll
            for (int r = 0; r < 16; r++) {
                bool lo = (r == 0) ? fprev : fl[r - 1];
                bool hi = (r == 15) ? flagB : fl[r];
                if (lo | hi) {
                    unsigned pk = lo ? (r > 0 ? v[r - 1] : kprev)
                                     : (r < 15 ? v[r + 1] : knext);
                    int idx  = (int)((~v[r]) & 127u);
                    int pidx = (int)((~pk)   & 127u);
                    unsigned us = ford(__float_as_uint(A[colw + idx]));
                    unsigned up = ford(__float_as_uint(A[colw + pidx]));
                    bool mefirst = (us > up) || ((us == up) && (idx < pidx));
                    int p    = 16 * m + r;
                    int pmin = lo ? p - 1 : p;
                    W[colw + idx] = g_wt[mefirst ? pmin : pmin + 1];
                }
            }
        }
    }
    __syncthreads();

    // ---- Phase 4: fused rsqrt + transpose back, coalesced store ----
    {
        int q = t >> 1, g = t & 1;
        #pragma unroll
        for (int blk = 0; blk < 4; blk++) {
            int cb = (8 * blk + 4 * g) * ASTRIDE + q;
            float o[4];
            #pragma unroll
            for (int j = 0; j < 4; j++) {
                float xv = A[cb + j * ASTRIDE];
                float rs;
                asm("rsqrt.approx.f32 %0, %1;" : "=f"(rs) : "f"(__fmaf_rn(xv, xv, EPS)));
                o[j] = W[cb + j * ASTRIDE] * rs;
            }
            *reinterpret_cast<float4*>(ob + (long long)q * HW + 8 * blk + 4 * g) =
                make_float4(o[0], o[1], o[2], o[3]);
        }
    }
}

// ---------------------------------------------------------------------------
extern "C" void kernel_launch(void* const* d_in, const int* in_sizes, int n_in,
                              void* d_out, int out_size) {
    const float* x  = (const float*)d_in[0];
    const float* wt = (const float*)d_in[1];
    if (n_in >= 2 && in_sizes[0] == Q) {  // defensive: metadata order swap
        const float* tmp = x; x = wt; wt = tmp;
    }
    float* out = (float*)d_out;

    softmax_wt_kernel<<<1, 32>>>(wt);

    int total_cols = 8 * HW;               // 524288
    int blocks = total_cols / NCOLS;       // 16384
    rank_weight_kernel<<<blocks, THREADS>>>(x, out);
}